// round 13
// baseline (speedup 1.0000x reference)
#include <cuda_runtime.h>
#include <math.h>

#define NTOT 8192
#define DD   128
#define EMBD 64

// ---------------- scratch (device globals; no allocations) ----------------
__device__ float g_A [NTOT*DD];          // compact rows
__device__ float g_P [7][NTOT*DD];       // L-pass K-slice partials (compact rows)
__device__ float g_PB[2][3][NTOT*DD];    // B-pass partials (compact rows)
__device__ float g_PE[2][3][NTOT*EMBD];  // E-pass partials (compact rows)
__device__ float g_Dk[2][NTOT*EMBD];     // compact rows
__device__ float g_Z [NTOT*EMBD];        // compact rows
__device__ int   g_cnt[NTOT];
__device__ int   g_nz[NTOT];             // nz row list (padded with 0)
__device__ int   g_rank[NTOT];           // original row -> compact index
__device__ int   g_nnz, g_npad, g_nm;

// transposed bf16 hi/lo operands ([C][NTOT], ORIGINAL row indexing, zeros on cnt=0)
__device__ unsigned short g_xt_hi [DD*NTOT];
__device__ unsigned short g_xt_lo [DD*NTOT];
__device__ unsigned short g_act_hi[DD*NTOT];
__device__ unsigned short g_act_lo[DD*NTOT];
__device__ unsigned short g_dt_hi [2][EMBD*NTOT];
__device__ unsigned short g_dt_lo [2][EMBD*NTOT];

// ---------------- helpers ----------------
__device__ __forceinline__ unsigned smem_u32(const void* p) {
    unsigned a;
    asm("{ .reg .u64 t; cvta.to.shared.u64 t, %1; cvt.u32.u64 %0, t; }" : "=r"(a) : "l"(p));
    return a;
}
#define SWZ(o) ((o) ^ (((o) >> 3) & 0x70))

#define LDSM4(d0,d1,d2,d3,addr) \
    asm volatile("ldmatrix.sync.aligned.m8n8.x4.shared.b16 {%0,%1,%2,%3}, [%4];" \
        : "=r"(d0), "=r"(d1), "=r"(d2), "=r"(d3) : "r"(addr))

#define MMA16816(c, a, b) \
    asm volatile("mma.sync.aligned.m16n8k16.row.col.f32.bf16.bf16.f32 " \
        "{%0,%1,%2,%3},{%4,%5,%6,%7},{%8,%9},{%0,%1,%2,%3};" \
        : "+f"((c)[0]), "+f"((c)[1]), "+f"((c)[2]), "+f"((c)[3]) \
        : "r"((a)[0]), "r"((a)[1]), "r"((a)[2]), "r"((a)[3]), \
          "r"((b)[0]), "r"((b)[1]))

#define CP16(dst, src) \
    asm volatile("cp.async.cg.shared.global [%0], [%1], 16;" :: "r"(dst), "l"(src))
#define CP_COMMIT() asm volatile("cp.async.commit_group;" ::: "memory")
#define CP_WAIT0()  asm volatile("cp.async.wait_group 0;" ::: "memory")

// bf16 hi/lo split of a float pair: hi = truncation (PRMT), lo = rn(x - hi)
__device__ __forceinline__ void split2(float f0, float f1, unsigned& hi, unsigned& lo) {
    unsigned u0 = __float_as_uint(f0), u1 = __float_as_uint(f1);
    unsigned h;
    asm("prmt.b32 %0, %1, %2, 0x7632;" : "=r"(h) : "r"(u0), "r"(u1));
    float h0 = __uint_as_float(u0 & 0xFFFF0000u);
    float h1 = __uint_as_float(u1 & 0xFFFF0000u);
    float r0 = f0 - h0, r1 = f1 - h1;
    unsigned l;
    asm("cvt.rn.bf16x2.f32 %0, %1, %2;" : "=r"(l) : "f"(r1), "f"(r0));
    hi = h; lo = l;
}

// ---------------- tiny kernels ----------------
__global__ void zero_cnt_kernel() {
    g_cnt[blockIdx.x*blockDim.x + threadIdx.x] = 0;
}
__global__ void count_kernel(const int* __restrict__ n_id) {
    atomicAdd(&g_cnt[n_id[blockIdx.x*blockDim.x + threadIdx.x]], 1);
}

// deterministic compaction scan: nz list, rank map, nnz/npad/nm
__global__ void scan_kernel() {
    __shared__ int ps[256];
    const int t = threadIdx.x;
    const int base = t * 32;
    int loc = 0;
    #pragma unroll
    for (int i = 0; i < 32; i++) loc += (g_cnt[base + i] > 0);
    ps[t] = loc;
    __syncthreads();
    for (int d = 1; d < 256; d <<= 1) {
        int v = (t >= d) ? ps[t - d] : 0;
        __syncthreads();
        ps[t] += v;
        __syncthreads();
    }
    int pos = ps[t] - loc;   // exclusive prefix
    for (int i = 0; i < 32; i++) {
        int r = base + i;
        if (g_cnt[r] > 0) { g_nz[pos] = r; g_rank[r] = pos; pos++; }
    }
    if (t == 255) {
        int nnz = ps[255];
        g_nnz = nnz;
        int npad = (nnz + 63) & ~63;
        g_npad = npad;
        g_nm = npad >> 6;
    }
    __syncthreads();
    int nnz = g_nnz;
    for (int j = nnz + t; j < NTOT; j += 256) g_nz[j] = 0;
}

// ---------------- transpose + bf16-split: full original rows ----------------
// SRC 0: x (dense). SRC 2/3: g_Dk[0/1] (compact rows scattered to original idx,
// zero rows where cnt==0). Phase-2 stores coalesced: one warp per column.
template<int C, int SRC>
__global__ __launch_bounds__(256) void tsplit(const float* __restrict__ xext)
{
    const float* in;
    unsigned short *hi, *lo;
    if (SRC == 0)      { in = xext;    hi = g_xt_hi;    lo = g_xt_lo; }
    else if (SRC == 2) { in = g_Dk[0]; hi = g_dt_hi[0]; lo = g_dt_lo[0]; }
    else               { in = g_Dk[1]; hi = g_dt_hi[1]; lo = g_dt_lo[1]; }

    __shared__ float tile[64][C + 4];
    const int t  = threadIdx.x;
    const int r0 = blockIdx.x * 64;
    constexpr int F4 = C / 4;
    #pragma unroll
    for (int i = 0; i < 64*F4/256; i++) {
        int u = t + i*256;
        int row = u / F4, c4 = u % F4;
        float4 v;
        if (SRC == 0) {
            v = *(const float4*)&in[(size_t)(r0+row)*C + c4*4];
        } else {
            int r = r0 + row;
            if (g_cnt[r] > 0)
                v = *(const float4*)&in[(size_t)g_rank[r]*C + c4*4];
            else
                v = make_float4(0.f, 0.f, 0.f, 0.f);
        }
        tile[row][c4*4+0] = v.x; tile[row][c4*4+1] = v.y;
        tile[row][c4*4+2] = v.z; tile[row][c4*4+3] = v.w;
    }
    __syncthreads();
    const int wid = t >> 5, lane = t & 31;
    const int r = 2*lane;
    for (int c = wid; c < C; c += 8) {
        unsigned h, l;
        split2(tile[r][c], tile[r+1][c], h, l);
        *(unsigned*)&hi[(size_t)c*NTOT + r0 + r] = h;
        *(unsigned*)&lo[(size_t)c*NTOT + r0 + r] = l;
    }
}

// ---- fused: A_c[j] = x[nz[j]] - tau*sum(P[s][j]); act (original idx) = cnt*A --
__global__ __launch_bounds__(256) void combine_tsplit(const float* __restrict__ x,
                                                      const float* __restrict__ taup)
{
    __shared__ float tile[64][DD + 4];
    const int t  = threadIdx.x;
    const int r0 = blockIdx.x * 64;
    const float tv = taup[0];
    #pragma unroll
    for (int i = 0; i < 8; i++) {
        int u = t + i*256;
        int row = u >> 5, c4 = u & 31;
        int r = r0 + row;
        int cn_i = g_cnt[r];
        if (cn_i > 0) {
            int j = g_rank[r];
            size_t oc = (size_t)j*DD + c4*4;
            float4 xv = *(const float4*)&x[(size_t)r*DD + c4*4];
            float4 ps = make_float4(0.f, 0.f, 0.f, 0.f);
            #pragma unroll
            for (int s = 0; s < 7; s++) {
                float4 p = *(const float4*)&g_P[s][oc];
                ps.x += p.x; ps.y += p.y; ps.z += p.z; ps.w += p.w;
            }
            float4 a;
            a.x = xv.x - tv*ps.x; a.y = xv.y - tv*ps.y;
            a.z = xv.z - tv*ps.z; a.w = xv.w - tv*ps.w;
            *(float4*)&g_A[oc] = a;
            float cn = (float)cn_i;
            tile[row][c4*4+0] = cn*a.x; tile[row][c4*4+1] = cn*a.y;
            tile[row][c4*4+2] = cn*a.z; tile[row][c4*4+3] = cn*a.w;
        } else {
            tile[row][c4*4+0] = 0.f; tile[row][c4*4+1] = 0.f;
            tile[row][c4*4+2] = 0.f; tile[row][c4*4+3] = 0.f;
        }
    }
    __syncthreads();
    const int wid = t >> 5, lane = t & 31;
    const int r = 2*lane;
    for (int c = wid; c < DD; c += 8) {
        unsigned h, l;
        split2(tile[r][c], tile[r+1][c], h, l);
        *(unsigned*)&g_act_hi[(size_t)c*NTOT + r0 + r] = h;
        *(unsigned*)&g_act_lo[(size_t)c*NTOT + r0 + r] = l;
    }
}

// ---------------- HMMA GEMM: M-compacted rows, full K, persistent loop ------
// MODE 0: Mat=L rows nz,    X=xt  -> g_P[s]      (NB=128, S=7)
// MODE 1: Mat=K[y] rows nz, X=act -> g_PB[y][s]  (NB=128, S=3)
// MODE 2: Mat=K[y] rows nz, X=dt  -> g_PE[y][s]  (NB=64,  S=3)
template<int NB, int MODE>
__global__ __launch_bounds__(256, 2) void gemm_hmma(const float* __restrict__ Mb)
{
    extern __shared__ char smem[];
    __shared__ int s_nzr[64];
    constexpr int NF  = NB / 32;
    constexpr int XSZ = NB * 128;
    constexpr int XU  = NB / 32;
    constexpr int S   = (MODE == 0) ? 7 : 3;

    const int t = threadIdx.x, lane = t & 31, w = t >> 5;
    const int wm = w & 1, wn = w >> 1;
    const int NM  = g_nm;
    const int NT  = (MODE == 0) ? NM : 2*NM;
    const unsigned su = smem_u32(smem);

    for (int q = blockIdx.x; q < NT*S; q += gridDim.x) {
        const int tile = q % NT;
        const int s    = q / NT;
        const int m    = (MODE == 0) ? tile : (tile % NM);
        const int y    = (MODE == 0) ? 0    : (tile / NM);
        const int c0   = (s * 128) / S;
        const int c1   = ((s + 1) * 128) / S;

        const float* Mat = (MODE == 0) ? Mb : Mb + (size_t)y * NTOT * NTOT;
        const unsigned short *XH, *XL;
        if (MODE == 0)      { XH = g_xt_hi;    XL = g_xt_lo; }
        else if (MODE == 1) { XH = g_act_hi;   XL = g_act_lo; }
        else                { XH = g_dt_hi[y]; XL = g_dt_lo[y]; }

        __syncthreads();   // all warps done with previous item's s_nzr
        if (t < 64) s_nzr[t] = g_nz[m*64 + t];
        __syncthreads();

        float acc[2][NF][4];
        #pragma unroll
        for (int mf = 0; mf < 2; mf++)
            #pragma unroll
            for (int nf = 0; nf < NF; nf++)
                #pragma unroll
                for (int j = 0; j < 4; j++) acc[mf][nf][j] = 0.f;

        float4 mv[4];

        auto LDG_MV = [&](int c) {
            const int k0 = c * 64;
            #pragma unroll
            for (int i = 0; i < 4; i++) {
                int u = t + (i << 8);
                int row = u >> 4, qd = u & 15;
                mv[i] = *(const float4*)&Mat[(size_t)s_nzr[row]*NTOT + k0 + (qd << 2)];
            }
        };
        auto FILL = [&](int c, int st) {
            char* aH = smem + st*16384;
            char* aL = aH + 8192;
            #pragma unroll
            for (int i = 0; i < 4; i++) {
                int u = t + (i << 8);
                int row = u >> 4, qd = u & 15;
                unsigned h0, l0, h1, l1;
                split2(mv[i].x, mv[i].y, h0, l0);
                split2(mv[i].z, mv[i].w, h1, l1);
                unsigned off = SWZ((unsigned)(row*128 + qd*8));
                *(uint2*)(aH + off) = make_uint2(h0, h1);
                *(uint2*)(aL + off) = make_uint2(l0, l1);
            }
            const int k0 = c * 64;
            const unsigned xHb = su + 32768 + st*2*XSZ;
            #pragma unroll
            for (int i = 0; i < XU; i++) {
                int u = t + (i << 8);
                unsigned off = SWZ((unsigned)((u >> 3)*128 + (u & 7)*16));
                size_t o = (size_t)(u >> 3)*NTOT + k0 + ((u & 7) << 3);
                CP16(xHb + off,       (const void*)&XH[o]);
                CP16(xHb + XSZ + off, (const void*)&XL[o]);
            }
            CP_COMMIT();
        };

        LDG_MV(c0);
        FILL(c0, 0);
        if (c0 + 1 < c1) LDG_MV(c0 + 1);
        CP_WAIT0();
        __syncthreads();

        int st = 0;
        for (int c = c0; c < c1; c++) {
            const unsigned aHb = su + st*16384;
            const unsigned aLb = aHb + 8192;
            const unsigned xHb = su + 32768 + st*2*XSZ;
            const unsigned xLb = xHb + XSZ;

            auto KSTEP = [&](int kk) {
                const int kc2 = kk * 32;
                unsigned ah[2][4], al[2][4];
                #pragma unroll
                for (int mf = 0; mf < 2; mf++) {
                    int row = wm*32 + mf*16 + (lane & 15);
                    int kb  = kc2 + ((lane >> 4) << 4);
                    unsigned off = SWZ((unsigned)(row*128 + kb));
                    LDSM4(ah[mf][0], ah[mf][1], ah[mf][2], ah[mf][3], aHb + off);
                    LDSM4(al[mf][0], al[mf][1], al[mf][2], al[mf][3], aLb + off);
                }
                unsigned bh[NF][2], bl[NF][2];
                #pragma unroll
                for (int g = 0; g < NF/2; g++) {
                    int n  = wn*(NB/4) + g*16 + ((lane >> 4) << 3) + (lane & 7);
                    int kb = kc2 + (((lane >> 3) & 1) << 4);
                    unsigned off = SWZ((unsigned)(n*128 + kb));
                    LDSM4(bh[2*g][0], bh[2*g][1], bh[2*g+1][0], bh[2*g+1][1], xHb + off);
                    LDSM4(bl[2*g][0], bl[2*g][1], bl[2*g+1][0], bl[2*g+1][1], xLb + off);
                }
                #pragma unroll
                for (int nf = 0; nf < NF; nf++)
                    #pragma unroll
                    for (int mf = 0; mf < 2; mf++) MMA16816(acc[mf][nf], ah[mf], bh[nf]);
                #pragma unroll
                for (int nf = 0; nf < NF; nf++)
                    #pragma unroll
                    for (int mf = 0; mf < 2; mf++) MMA16816(acc[mf][nf], ah[mf], bl[nf]);
                #pragma unroll
                for (int nf = 0; nf < NF; nf++)
                    #pragma unroll
                    for (int mf = 0; mf < 2; mf++) MMA16816(acc[mf][nf], al[mf], bh[nf]);
            };

            KSTEP(0);
            KSTEP(1);
            if (c + 1 < c1) {
                FILL(c + 1, st ^ 1);
                if (c + 2 < c1) LDG_MV(c + 2);
            }
            KSTEP(2);
            KSTEP(3);
            if (c + 1 < c1) {
                CP_WAIT0();
                __syncthreads();
            }
            st ^= 1;
        }

        // epilogue: write this slice's partial (compact rows)
        const int gid = lane >> 2, tig = lane & 3;
        float* O;
        int stride;
        if (MODE == 0)      { O = g_P[s];     stride = DD; }
        else if (MODE == 1) { O = g_PB[y][s]; stride = DD; }
        else                { O = g_PE[y][s]; stride = EMBD; }
        #pragma unroll
        for (int mf = 0; mf < 2; mf++) {
            int r = m*64 + wm*32 + mf*16 + gid;
            #pragma unroll
            for (int nf = 0; nf < NF; nf++) {
                int cc = wn*(NB/4) + nf*8 + 2*tig;
                *(float2*)&O[(size_t)r*stride + cc]     = make_float2(acc[mf][nf][0], acc[mf][nf][1]);
                *(float2*)&O[(size_t)(r+8)*stride + cc] = make_float2(acc[mf][nf][2], acc[mf][nf][3]);
            }
        }
    }
}

// ---------------- small fused projections (compact rows) ----------------
__global__ __launch_bounds__(256) void zd_kernel(const float* __restrict__ W)
{
    const int t  = threadIdx.x;
    const int r0 = blockIdx.x * 32;
    if (r0 >= g_npad) return;

    __shared__ float As [32][128];
    __shared__ float B0s[32][128];
    __shared__ float B1s[32][128];

    const int e  = t & 63;
    const int ry = t >> 6;

    #pragma unroll
    for (int i = 0; i < 4; i++) {
        int f = t + i*256;
        int row = f >> 5, c4 = f & 31;
        size_t o = (size_t)(r0+row)*DD + 4*c4;
        *(float4*)&As[row][4*c4] = *(const float4*)&g_A[o];
        float4 b0 = make_float4(0,0,0,0), b1 = make_float4(0,0,0,0);
        #pragma unroll
        for (int s = 0; s < 3; s++) {
            float4 p0 = *(const float4*)&g_PB[0][s][o];
            float4 p1 = *(const float4*)&g_PB[1][s][o];
            b0.x += p0.x; b0.y += p0.y; b0.z += p0.z; b0.w += p0.w;
            b1.x += p1.x; b1.y += p1.y; b1.z += p1.z; b1.w += p1.w;
        }
        *(float4*)&B0s[row][4*c4] = b0;
        *(float4*)&B1s[row][4*c4] = b1;
    }
    __syncthreads();

    float accZ[8], accD0[8], accD1[8];
    #pragma unroll
    for (int s = 0; s < 8; s++) { accZ[s] = 0.f; accD0[s] = 0.f; accD1[s] = 0.f; }

    for (int f = 0; f < 128; f++) {
        float wz0 = W[( 0  + f)*64 + e];
        float wz1 = W[(128 + f)*64 + e];
        float wz2 = W[(256 + f)*64 + e];
        float w00 = W[(384 + f)*64 + e];
        float w01 = W[(512 + f)*64 + e];
        float w10 = W[(640 + f)*64 + e];
        float w11 = W[(768 + f)*64 + e];
        #pragma unroll
        for (int s = 0; s < 8; s++) {
            int r = ry + 4*s;
            float a  = As [r][f];
            float b0 = B0s[r][f];
            float b1 = B1s[r][f];
            accZ [s] += a*wz0 + b0*wz1 + b1*wz2;
            accD0[s] += b0*w00 + b1*w01;
            accD1[s] += b0*w10 + b1*w11;
        }
    }
    #pragma unroll
    for (int s = 0; s < 8; s++) {
        int j = r0 + ry + 4*s;
        float cn = (float)g_cnt[g_nz[j]];
        g_Z    [(size_t)j*EMBD + e] = accZ[s];
        g_Dk[0][(size_t)j*EMBD + e] = cn * accD0[s];
        g_Dk[1][(size_t)j*EMBD + e] = cn * accD1[s];
    }
}

__global__ void final_kernel(const int* __restrict__ n_id,
                             const float* __restrict__ b,
                             float* __restrict__ out)
{
    int idx = blockIdx.x*blockDim.x + threadIdx.x;
    int j = idx >> 6, e = idx & 63;
    int cr = g_rank[n_id[j]];
    size_t zr = (size_t)cr*EMBD + e;
    float ev = 0.f;
    #pragma unroll
    for (int s = 0; s < 3; s++) ev += g_PE[0][s][zr] + g_PE[1][s][zr];
    out[idx] = tanhf(g_Z[zr] + ev + b[e]);
}

// ---------------- launch ----------------
extern "C" void kernel_launch(void* const* d_in, const int* in_sizes, int n_in,
                              void* d_out, int out_size)
{
    const float* x    = (const float*)d_in[0];
    const float* K    = (const float*)d_in[1];
    const float* L    = (const float*)d_in[2];
    const float* tau  = (const float*)d_in[3];
    const float* W    = (const float*)d_in[4];
    const float* b    = (const float*)d_in[5];
    const int*   n_id = (const int*)  d_in[6];
    float* out = (float*)d_out;

    const int SM128 = 32768 + 4*128*128;   // 98304
    const int SM64  = 32768 + 4*64*128;    // 65536
    cudaFuncSetAttribute(gemm_hmma<128,0>, cudaFuncAttributeMaxDynamicSharedMemorySize, SM128);
    cudaFuncSetAttribute(gemm_hmma<128,1>, cudaFuncAttributeMaxDynamicSharedMemorySize, SM128);
    cudaFuncSetAttribute(gemm_hmma<64,2>,  cudaFuncAttributeMaxDynamicSharedMemorySize, SM64);

    const int GRID = 304;   // 2 CTAs/SM x 152 SMs

    zero_cnt_kernel<<<NTOT/256, 256>>>();
    count_kernel   <<<NTOT/256, 256>>>(n_id);
    scan_kernel    <<<1, 256>>>();

    // x^T split (full); L@x partials on nz rows (7 K-slices); fused combine
    tsplit<128,0><<<NTOT/64, 256>>>(x);
    gemm_hmma<128,0><<<GRID, 256, SM128>>>(L);
    combine_tsplit<<<NTOT/64, 256>>>(x, tau);

    // B_k = K[k] @ Ac  (rows compacted, full K, 3 K-slices)
    gemm_hmma<128,1><<<GRID, 256, SM128>>>(K);

    // Z and D_k (sums B partials inline)
    zd_kernel<<<NTOT/32, 256>>>(W);

    // Dk^T splits (scatter to original idx, zero rows); E_k = K[k] @ D_k
    tsplit<64,2><<<NTOT/64, 256>>>(nullptr);
    tsplit<64,3><<<NTOT/64, 256>>>(nullptr);
    gemm_hmma<64,2><<<GRID, 256, SM64>>>(K);

    final_kernel<<<(NTOT*EMBD)/256, 256>>>(n_id, b, out);
}

// round 14
// speedup vs baseline: 1.1906x; 1.1906x over previous
#include <cuda_runtime.h>
#include <math.h>

#define NTOT 8192
#define DD   128
#define EMBD 64
#define SL   7

// ---------------- scratch (device globals; no allocations) ----------------
__device__ float g_A [NTOT*DD];           // compact rows
__device__ float g_P [SL][NTOT*DD];       // L-pass K-slice partials
__device__ float g_PB[2][SL][NTOT*DD];    // B-pass partials
__device__ float g_PE[2][SL][NTOT*EMBD];  // E-pass partials
__device__ float g_Dk[2][NTOT*EMBD];      // compact rows
__device__ float g_Z [NTOT*EMBD];         // compact rows
__device__ int   g_cnt[NTOT];
__device__ int   g_nz[NTOT];              // nz row list (padded with 0)
__device__ int   g_rank[NTOT];            // original row -> compact index
__device__ int   g_nnz, g_npad, g_nm;

// transposed bf16 hi/lo operands ([C][NTOT]; xt original idx, act/dt compact)
__device__ unsigned short g_xt_hi [DD*NTOT];
__device__ unsigned short g_xt_lo [DD*NTOT];
__device__ unsigned short g_act_hi[DD*NTOT];
__device__ unsigned short g_act_lo[DD*NTOT];
__device__ unsigned short g_dt_hi [2][EMBD*NTOT];
__device__ unsigned short g_dt_lo [2][EMBD*NTOT];

// compacted bf16 K (rows+cols nz, row stride = npad), written by B-pass
__device__ unsigned short g_kc_hi[2][(size_t)NTOT*NTOT];
__device__ unsigned short g_kc_lo[2][(size_t)NTOT*NTOT];

// ---------------- helpers ----------------
__device__ __forceinline__ unsigned smem_u32(const void* p) {
    unsigned a;
    asm("{ .reg .u64 t; cvta.to.shared.u64 t, %1; cvt.u32.u64 %0, t; }" : "=r"(a) : "l"(p));
    return a;
}
#define SWZ(o) ((o) ^ (((o) >> 3) & 0x70))

#define LDSM4(d0,d1,d2,d3,addr) \
    asm volatile("ldmatrix.sync.aligned.m8n8.x4.shared.b16 {%0,%1,%2,%3}, [%4];" \
        : "=r"(d0), "=r"(d1), "=r"(d2), "=r"(d3) : "r"(addr))

#define MMA16816(c, a, b) \
    asm volatile("mma.sync.aligned.m16n8k16.row.col.f32.bf16.bf16.f32 " \
        "{%0,%1,%2,%3},{%4,%5,%6,%7},{%8,%9},{%0,%1,%2,%3};" \
        : "+f"((c)[0]), "+f"((c)[1]), "+f"((c)[2]), "+f"((c)[3]) \
        : "r"((a)[0]), "r"((a)[1]), "r"((a)[2]), "r"((a)[3]), \
          "r"((b)[0]), "r"((b)[1]))

#define CP16(dst, src) \
    asm volatile("cp.async.cg.shared.global [%0], [%1], 16;" :: "r"(dst), "l"(src))
#define CP_COMMIT() asm volatile("cp.async.commit_group;" ::: "memory")
#define CP_WAIT0()  asm volatile("cp.async.wait_group 0;" ::: "memory")

// bf16 hi/lo split of a float pair: hi = truncation (PRMT), lo = rn(x - hi)
__device__ __forceinline__ void split2(float f0, float f1, unsigned& hi, unsigned& lo) {
    unsigned u0 = __float_as_uint(f0), u1 = __float_as_uint(f1);
    unsigned h;
    asm("prmt.b32 %0, %1, %2, 0x7632;" : "=r"(h) : "r"(u0), "r"(u1));
    float h0 = __uint_as_float(u0 & 0xFFFF0000u);
    float h1 = __uint_as_float(u1 & 0xFFFF0000u);
    float r0 = f0 - h0, r1 = f1 - h1;
    unsigned l;
    asm("cvt.rn.bf16x2.f32 %0, %1, %2;" : "=r"(l) : "f"(r1), "f"(r0));
    hi = h; lo = l;
}

// ---------------- tiny kernels ----------------
__global__ void zero_cnt_kernel() {
    g_cnt[blockIdx.x*blockDim.x + threadIdx.x] = 0;
}
__global__ void count_kernel(const int* __restrict__ n_id) {
    atomicAdd(&g_cnt[n_id[blockIdx.x*blockDim.x + threadIdx.x]], 1);
}

// deterministic compaction scan
__global__ void scan_kernel() {
    __shared__ int ps[256];
    const int t = threadIdx.x;
    const int base = t * 32;
    int loc = 0;
    #pragma unroll
    for (int i = 0; i < 32; i++) loc += (g_cnt[base + i] > 0);
    ps[t] = loc;
    __syncthreads();
    for (int d = 1; d < 256; d <<= 1) {
        int v = (t >= d) ? ps[t - d] : 0;
        __syncthreads();
        ps[t] += v;
        __syncthreads();
    }
    int pos = ps[t] - loc;
    for (int i = 0; i < 32; i++) {
        int r = base + i;
        if (g_cnt[r] > 0) { g_nz[pos] = r; g_rank[r] = pos; pos++; }
    }
    if (t == 255) {
        int nnz = ps[255];
        g_nnz = nnz;
        int npad = (nnz + 63) & ~63;
        g_npad = npad;
        g_nm = npad >> 6;
    }
    __syncthreads();
    int nnz = g_nnz;
    for (int j = nnz + t; j < NTOT; j += 256) g_nz[j] = 0;
}

// ---------------- transpose + bf16-split (coalesced stores) ----------------
// SRC 0: x full original. SRC 2/3: g_Dk compact rows, zero-pad to npad.
template<int C, int SRC>
__global__ __launch_bounds__(256) void tsplit(const float* __restrict__ xext)
{
    const float* in;
    unsigned short *hi, *lo;
    if (SRC == 0)      { in = xext;    hi = g_xt_hi;    lo = g_xt_lo; }
    else if (SRC == 2) { in = g_Dk[0]; hi = g_dt_hi[0]; lo = g_dt_lo[0]; }
    else               { in = g_Dk[1]; hi = g_dt_hi[1]; lo = g_dt_lo[1]; }

    const int t  = threadIdx.x;
    const int r0 = blockIdx.x * 64;
    int lim = NTOT;
    if (SRC != 0) {
        if (r0 >= g_npad) return;
        lim = g_nnz;
    }

    __shared__ float tile[64][C + 4];
    constexpr int F4 = C / 4;
    #pragma unroll
    for (int i = 0; i < 64*F4/256; i++) {
        int u = t + i*256;
        int row = u / F4, c4 = u % F4;
        if (SRC == 0 || r0 + row < lim) {
            float4 v = *(const float4*)&in[(size_t)(r0+row)*C + c4*4];
            tile[row][c4*4+0] = v.x; tile[row][c4*4+1] = v.y;
            tile[row][c4*4+2] = v.z; tile[row][c4*4+3] = v.w;
        } else {
            tile[row][c4*4+0] = 0.f; tile[row][c4*4+1] = 0.f;
            tile[row][c4*4+2] = 0.f; tile[row][c4*4+3] = 0.f;
        }
    }
    __syncthreads();
    const int wid = t >> 5, lane = t & 31;
    const int r = 2*lane;
    for (int c = wid; c < C; c += 8) {
        unsigned h, l;
        split2(tile[r][c], tile[r+1][c], h, l);
        *(unsigned*)&hi[(size_t)c*NTOT + r0 + r] = h;
        *(unsigned*)&lo[(size_t)c*NTOT + r0 + r] = l;
    }
}

// ---- fused: A_c[j] = x[nz[j]] - tau*sum(P); act (compact) = cnt*A ----
__global__ __launch_bounds__(256) void combine_tsplit(const float* __restrict__ x,
                                                      const float* __restrict__ taup)
{
    const int t  = threadIdx.x;
    const int r0 = blockIdx.x * 64;
    if (r0 >= g_npad) return;
    const int nnz = g_nnz;
    const float tv = taup[0];

    __shared__ float tile[64][DD + 4];
    #pragma unroll
    for (int i = 0; i < 8; i++) {
        int u = t + i*256;
        int row = u >> 5, c4 = u & 31;
        int j = r0 + row;
        if (j < nnz) {
            int orow = g_nz[j];
            float cn = (float)g_cnt[orow];
            size_t oc = (size_t)j*DD + c4*4;
            float4 xv = *(const float4*)&x[(size_t)orow*DD + c4*4];
            float4 ps = make_float4(0.f, 0.f, 0.f, 0.f);
            #pragma unroll
            for (int s = 0; s < SL; s++) {
                float4 p = *(const float4*)&g_P[s][oc];
                ps.x += p.x; ps.y += p.y; ps.z += p.z; ps.w += p.w;
            }
            float4 a;
            a.x = xv.x - tv*ps.x; a.y = xv.y - tv*ps.y;
            a.z = xv.z - tv*ps.z; a.w = xv.w - tv*ps.w;
            *(float4*)&g_A[oc] = a;
            tile[row][c4*4+0] = cn*a.x; tile[row][c4*4+1] = cn*a.y;
            tile[row][c4*4+2] = cn*a.z; tile[row][c4*4+3] = cn*a.w;
        } else {
            tile[row][c4*4+0] = 0.f; tile[row][c4*4+1] = 0.f;
            tile[row][c4*4+2] = 0.f; tile[row][c4*4+3] = 0.f;
        }
    }
    __syncthreads();
    const int wid = t >> 5, lane = t & 31;
    const int r = 2*lane;
    for (int c = wid; c < DD; c += 8) {
        unsigned h, l;
        split2(tile[r][c], tile[r+1][c], h, l);
        *(unsigned*)&g_act_hi[(size_t)c*NTOT + r0 + r] = h;
        *(unsigned*)&g_act_lo[(size_t)c*NTOT + r0 + r] = l;
    }
}

// ---------------- HMMA GEMM: persistent, S=7 slices per output tile --------
// MODE 0: Mat=L rows nz, X=xt (full K)      -> g_P[s]
// MODE 1: Mat=K[y] rows+cols nz (gather+split, ALSO writes g_kc), X=act -> g_PB[y][s]
// MODE 2: A = g_kc (cp.async), X=dt         -> g_PE[y][s]
template<int NB, int MODE>
__global__ __launch_bounds__(256, 2) void gemm_hmma(const float* __restrict__ Mb)
{
    extern __shared__ char smem[];
    __shared__ int s_nzr[64];
    constexpr int NF  = NB / 32;
    constexpr int XSZ = NB * 128;
    constexpr int XU  = NB / 32;

    const int t = threadIdx.x, lane = t & 31, w = t >> 5;
    const int wm = w & 1, wn = w >> 1;
    const int NM   = g_nm;
    const int NPAD = g_npad;
    const int NT   = (MODE == 0) ? NM : 2*NM;
    const int NC   = (MODE == 0) ? 128 : NM;
    const unsigned su = smem_u32(smem);

    for (int q = blockIdx.x; q < NT*SL; q += gridDim.x) {
        const int tile = q % NT;
        const int s    = q / NT;
        const int m    = (MODE == 0) ? tile : (tile % NM);
        const int y    = (MODE == 0) ? 0    : (tile / NM);
        const int c0   = (s * NC) / SL;
        const int c1   = ((s + 1) * NC) / SL;

        const float* Mat = (MODE == 0) ? Mb : Mb + (size_t)y * NTOT * NTOT;
        const unsigned short *XH, *XL;
        if (MODE == 0)      { XH = g_xt_hi;    XL = g_xt_lo; }
        else if (MODE == 1) { XH = g_act_hi;   XL = g_act_lo; }
        else                { XH = g_dt_hi[y]; XL = g_dt_lo[y]; }

        __syncthreads();   // smem stage + s_nzr reuse across items
        if (MODE != 2) {
            if (t < 64) s_nzr[t] = g_nz[m*64 + t];
            __syncthreads();
        }

        float acc[2][NF][4];
        #pragma unroll
        for (int mf = 0; mf < 2; mf++)
            #pragma unroll
            for (int nf = 0; nf < NF; nf++)
                #pragma unroll
                for (int j = 0; j < 4; j++) acc[mf][nf][j] = 0.f;

        float mv[16];

        auto LDG_MV = [&](int c) {
            if (MODE == 2) return;
            const int k0 = c * 64;
            #pragma unroll
            for (int i = 0; i < 4; i++) {
                int u = t + (i << 8);
                int row = u >> 4, qd = u & 15;
                size_t rbase = (size_t)s_nzr[row] * NTOT;
                if (MODE == 0) {
                    *(float4*)&mv[i*4] = *(const float4*)&Mat[rbase + k0 + (qd << 2)];
                } else {
                    #pragma unroll
                    for (int j = 0; j < 4; j++)
                        mv[i*4+j] = Mat[rbase + g_nz[k0 + qd*4 + j]];
                }
            }
        };
        auto FILL = [&](int c, int st) {
            const int k0 = c * 64;
            if (MODE == 2) {
                const unsigned aHb = su + st*16384;
                #pragma unroll
                for (int i = 0; i < 2; i++) {
                    int u = t + (i << 8);
                    int row = u >> 3, j8 = u & 7;
                    unsigned off = SWZ((unsigned)(row*128 + j8*16));
                    size_t o = (size_t)(m*64 + row)*NPAD + k0 + j8*8;
                    CP16(aHb + off,        (const void*)&g_kc_hi[y][o]);
                    CP16(aHb + 8192 + off, (const void*)&g_kc_lo[y][o]);
                }
            } else {
                char* aH = smem + st*16384;
                char* aL = aH + 8192;
                #pragma unroll
                for (int i = 0; i < 4; i++) {
                    int u = t + (i << 8);
                    int row = u >> 4, qd = u & 15;
                    unsigned h0, l0, h1, l1;
                    split2(mv[i*4+0], mv[i*4+1], h0, l0);
                    split2(mv[i*4+2], mv[i*4+3], h1, l1);
                    unsigned off = SWZ((unsigned)(row*128 + qd*8));
                    *(uint2*)(aH + off) = make_uint2(h0, h1);
                    *(uint2*)(aL + off) = make_uint2(l0, l1);
                    if (MODE == 1) {
                        size_t ko = (size_t)(m*64 + row)*NPAD + k0 + qd*4;
                        *(uint2*)&g_kc_hi[y][ko] = make_uint2(h0, h1);
                        *(uint2*)&g_kc_lo[y][ko] = make_uint2(l0, l1);
                    }
                }
            }
            const unsigned xHb = su + 32768 + st*2*XSZ;
            #pragma unroll
            for (int i = 0; i < XU; i++) {
                int u = t + (i << 8);
                unsigned off = SWZ((unsigned)((u >> 3)*128 + (u & 7)*16));
                size_t o = (size_t)(u >> 3)*NTOT + k0 + ((u & 7) << 3);
                CP16(xHb + off,       (const void*)&XH[o]);
                CP16(xHb + XSZ + off, (const void*)&XL[o]);
            }
            CP_COMMIT();
        };

        LDG_MV(c0);
        FILL(c0, 0);
        if (c0 + 1 < c1) LDG_MV(c0 + 1);
        CP_WAIT0();
        __syncthreads();

        int st = 0;
        for (int c = c0; c < c1; c++) {
            const unsigned aHb = su + st*16384;
            const unsigned aLb = aHb + 8192;
            const unsigned xHb = su + 32768 + st*2*XSZ;
            const unsigned xLb = xHb + XSZ;

            auto KSTEP = [&](int kk) {
                const int kc2 = kk * 32;
                unsigned ah[2][4], al[2][4];
                #pragma unroll
                for (int mf = 0; mf < 2; mf++) {
                    int row = wm*32 + mf*16 + (lane & 15);
                    int kb  = kc2 + ((lane >> 4) << 4);
                    unsigned off = SWZ((unsigned)(row*128 + kb));
                    LDSM4(ah[mf][0], ah[mf][1], ah[mf][2], ah[mf][3], aHb + off);
                    LDSM4(al[mf][0], al[mf][1], al[mf][2], al[mf][3], aLb + off);
                }
                unsigned bh[NF][2], bl[NF][2];
                #pragma unroll
                for (int g = 0; g < NF/2; g++) {
                    int n  = wn*(NB/4) + g*16 + ((lane >> 4) << 3) + (lane & 7);
                    int kb = kc2 + (((lane >> 3) & 1) << 4);
                    unsigned off = SWZ((unsigned)(n*128 + kb));
                    LDSM4(bh[2*g][0], bh[2*g][1], bh[2*g+1][0], bh[2*g+1][1], xHb + off);
                    LDSM4(bl[2*g][0], bl[2*g][1], bl[2*g+1][0], bl[2*g+1][1], xLb + off);
                }
                #pragma unroll
                for (int nf = 0; nf < NF; nf++)
                    #pragma unroll
                    for (int mf = 0; mf < 2; mf++) MMA16816(acc[mf][nf], ah[mf], bh[nf]);
                #pragma unroll
                for (int nf = 0; nf < NF; nf++)
                    #pragma unroll
                    for (int mf = 0; mf < 2; mf++) MMA16816(acc[mf][nf], ah[mf], bl[nf]);
                #pragma unroll
                for (int nf = 0; nf < NF; nf++)
                    #pragma unroll
                    for (int mf = 0; mf < 2; mf++) MMA16816(acc[mf][nf], al[mf], bh[nf]);
            };

            KSTEP(0);
            KSTEP(1);
            if (c + 1 < c1) {
                FILL(c + 1, st ^ 1);
                if (c + 2 < c1) LDG_MV(c + 2);
            }
            KSTEP(2);
            KSTEP(3);
            if (c + 1 < c1) {
                CP_WAIT0();
                __syncthreads();
            }
            st ^= 1;
        }

        // epilogue: write this slice's partial (compact rows)
        const int gid = lane >> 2, tig = lane & 3;
        float* O;
        int stride;
        if (MODE == 0)      { O = g_P[s];     stride = DD; }
        else if (MODE == 1) { O = g_PB[y][s]; stride = DD; }
        else                { O = g_PE[y][s]; stride = EMBD; }
        #pragma unroll
        for (int mf = 0; mf < 2; mf++) {
            int r = m*64 + wm*32 + mf*16 + gid;
            #pragma unroll
            for (int nf = 0; nf < NF; nf++) {
                int cc = wn*(NB/4) + nf*8 + 2*tig;
                *(float2*)&O[(size_t)r*stride + cc]     = make_float2(acc[mf][nf][0], acc[mf][nf][1]);
                *(float2*)&O[(size_t)(r+8)*stride + cc] = make_float2(acc[mf][nf][2], acc[mf][nf][3]);
            }
        }
    }
}

// ---------------- small fused projections (compact rows) ----------------
__global__ __launch_bounds__(256) void zd_kernel(const float* __restrict__ W)
{
    const int t  = threadIdx.x;
    const int r0 = blockIdx.x * 32;
    if (r0 >= g_npad) return;

    __shared__ float As [32][128];
    __shared__ float B0s[32][128];
    __shared__ float B1s[32][128];

    const int e  = t & 63;
    const int ry = t >> 6;

    #pragma unroll
    for (int i = 0; i < 4; i++) {
        int f = t + i*256;
        int row = f >> 5, c4 = f & 31;
        size_t o = (size_t)(r0+row)*DD + 4*c4;
        *(float4*)&As[row][4*c4] = *(const float4*)&g_A[o];
        float4 b0 = make_float4(0,0,0,0), b1 = make_float4(0,0,0,0);
        #pragma unroll
        for (int s = 0; s < SL; s++) {
            float4 p0 = *(const float4*)&g_PB[0][s][o];
            float4 p1 = *(const float4*)&g_PB[1][s][o];
            b0.x += p0.x; b0.y += p0.y; b0.z += p0.z; b0.w += p0.w;
            b1.x += p1.x; b1.y += p1.y; b1.z += p1.z; b1.w += p1.w;
        }
        *(float4*)&B0s[row][4*c4] = b0;
        *(float4*)&B1s[row][4*c4] = b1;
    }
    __syncthreads();

    float accZ[8], accD0[8], accD1[8];
    #pragma unroll
    for (int s = 0; s < 8; s++) { accZ[s] = 0.f; accD0[s] = 0.f; accD1[s] = 0.f; }

    for (int f = 0; f < 128; f++) {
        float wz0 = W[( 0  + f)*64 + e];
        float wz1 = W[(128 + f)*64 + e];
        float wz2 = W[(256 + f)*64 + e];
        float w00 = W[(384 + f)*64 + e];
        float w01 = W[(512 + f)*64 + e];
        float w10 = W[(640 + f)*64 + e];
        float w11 = W[(768 + f)*64 + e];
        #pragma unroll
        for (int s = 0; s < 8; s++) {
            int r = ry + 4*s;
            float a  = As [r][f];
            float b0 = B0s[r][f];
            float b1 = B1s[r][f];
            accZ [s] += a*wz0 + b0*wz1 + b1*wz2;
            accD0[s] += b0*w00 + b1*w01;
            accD1[s] += b0*w10 + b1*w11;
        }
    }
    #pragma unroll
    for (int s = 0; s < 8; s++) {
        int j = r0 + ry + 4*s;
        float cn = (float)g_cnt[g_nz[j]];
        g_Z    [(size_t)j*EMBD + e] = accZ[s];
        g_Dk[0][(size_t)j*EMBD + e] = cn * accD0[s];
        g_Dk[1][(size_t)j*EMBD + e] = cn * accD1[s];
    }
}

__global__ void final_kernel(const int* __restrict__ n_id,
                             const float* __restrict__ b,
                             float* __restrict__ out)
{
    int idx = blockIdx.x*blockDim.x + threadIdx.x;
    int j = idx >> 6, e = idx & 63;
    int cr = g_rank[n_id[j]];
    size_t zr = (size_t)cr*EMBD + e;
    float ev = 0.f;
    #pragma unroll
    for (int s = 0; s < SL; s++) ev += g_PE[0][s][zr] + g_PE[1][s][zr];
    out[idx] = tanhf(g_Z[zr] + ev + b[e]);
}

// ---------------- launch ----------------
extern "C" void kernel_launch(void* const* d_in, const int* in_sizes, int n_in,
                              void* d_out, int out_size)
{
    const float* x    = (const float*)d_in[0];
    const float* K    = (const float*)d_in[1];
    const float* L    = (const float*)d_in[2];
    const float* tau  = (const float*)d_in[3];
    const float* W    = (const float*)d_in[4];
    const float* b    = (const float*)d_in[5];
    const int*   n_id = (const int*)  d_in[6];
    float* out = (float*)d_out;

    const int SM128 = 32768 + 4*128*128;   // 98304
    const int SM64  = 32768 + 4*64*128;    // 65536
    cudaFuncSetAttribute(gemm_hmma<128,0>, cudaFuncAttributeMaxDynamicSharedMemorySize, SM128);
    cudaFuncSetAttribute(gemm_hmma<128,1>, cudaFuncAttributeMaxDynamicSharedMemorySize, SM128);
    cudaFuncSetAttribute(gemm_hmma<64,2>,  cudaFuncAttributeMaxDynamicSharedMemorySize, SM64);

    const int GRID = 304;   // 2 CTAs/SM x 152 SMs

    zero_cnt_kernel<<<NTOT/256, 256>>>();
    count_kernel   <<<NTOT/256, 256>>>(n_id);
    scan_kernel    <<<1, 256>>>();

    // x^T split (full); L@x partials on nz rows (7 K-slices); fused combine
    tsplit<128,0><<<NTOT/64, 256>>>(x);
    gemm_hmma<128,0><<<GRID, 256, SM128>>>(L);
    combine_tsplit<<<NTOT/64, 256>>>(x, tau);

    // B_k = K[k] @ Ac (rows+cols compact; gathers K once, streams bf16 K out)
    gemm_hmma<128,1><<<GRID, 256, SM128>>>(K);

    // Z and D_k (sums B partials inline)
    zd_kernel<<<NTOT/32, 256>>>(W);

    // Dk^T splits (compact, zero-padded); E_k = K[k] @ D_k (A via cp.async)
    tsplit<64,2><<<NTOT/64, 256>>>(nullptr);
    tsplit<64,3><<<NTOT/64, 256>>>(nullptr);
    gemm_hmma<64,2><<<GRID, 256, SM64>>>(K);

    final_kernel<<<(NTOT*EMBD)/256, 256>>>(n_id, b, out);
}

// round 15
// speedup vs baseline: 1.3520x; 1.1356x over previous
#include <cuda_runtime.h>
#include <cuda_fp16.h>
#include <math.h>

#define NTOT 8192
#define DD   128
#define EMBD 64
#define SL   7

// ---------------- scratch (device globals; no allocations) ----------------
__device__ float g_A [NTOT*DD];           // compact rows
__device__ float g_P [SL][NTOT*DD];       // L-pass K-slice partials
__device__ float g_PB[2][SL][NTOT*DD];    // B-pass partials
__device__ float g_PE[2][SL][NTOT*EMBD];  // E-pass partials
__device__ float g_Dk[2][NTOT*EMBD];      // compact rows
__device__ float g_Z [NTOT*EMBD];         // compact rows
__device__ int   g_cnt[NTOT];
__device__ int   g_nz[NTOT];              // nz row list (padded with 0)
__device__ int   g_rank[NTOT];            // original row -> compact index
__device__ int   g_nnz, g_npad, g_nm;

// transposed fp16 X operands ([C][NTOT]; xt original idx, act/dt compact)
__device__ unsigned short g_xt [DD*NTOT];
__device__ unsigned short g_act[DD*NTOT];
__device__ unsigned short g_dt [2][EMBD*NTOT];

// compacted fp16 K limbs (rows+cols nz, row stride = npad), written by B-pass
__device__ unsigned short g_kc_hi[2][(size_t)NTOT*NTOT];
__device__ unsigned short g_kc_lo[2][(size_t)NTOT*NTOT];

// ---------------- helpers ----------------
__device__ __forceinline__ unsigned smem_u32(const void* p) {
    unsigned a;
    asm("{ .reg .u64 t; cvta.to.shared.u64 t, %1; cvt.u32.u64 %0, t; }" : "=r"(a) : "l"(p));
    return a;
}
#define SWZ(o) ((o) ^ (((o) >> 3) & 0x70))

#define LDSM4(d0,d1,d2,d3,addr) \
    asm volatile("ldmatrix.sync.aligned.m8n8.x4.shared.b16 {%0,%1,%2,%3}, [%4];" \
        : "=r"(d0), "=r"(d1), "=r"(d2), "=r"(d3) : "r"(addr))

#define MMA16816(c, a, b) \
    asm volatile("mma.sync.aligned.m16n8k16.row.col.f32.f16.f16.f32 " \
        "{%0,%1,%2,%3},{%4,%5,%6,%7},{%8,%9},{%0,%1,%2,%3};" \
        : "+f"((c)[0]), "+f"((c)[1]), "+f"((c)[2]), "+f"((c)[3]) \
        : "r"((a)[0]), "r"((a)[1]), "r"((a)[2]), "r"((a)[3]), \
          "r"((b)[0]), "r"((b)[1]))

#define CP16(dst, src) \
    asm volatile("cp.async.cg.shared.global [%0], [%1], 16;" :: "r"(dst), "l"(src))
#define CP_COMMIT() asm volatile("cp.async.commit_group;" ::: "memory")
#define CP_WAIT0()  asm volatile("cp.async.wait_group 0;" ::: "memory")

// pack float pair to f16x2 (rn)
__device__ __forceinline__ unsigned pack2h(float f0, float f1) {
    unsigned r;
    asm("cvt.rn.f16x2.f32 %0, %1, %2;" : "=r"(r) : "f"(f1), "f"(f0));
    return r;
}
// fp16 hi/lo limb split of a float pair: hi = rn(v), lo = rn(v - hi)
__device__ __forceinline__ void split2h(float f0, float f1, unsigned& hi, unsigned& lo) {
    unsigned h = pack2h(f0, f1);
    __half2 hh = *reinterpret_cast<__half2*>(&h);
    float h0 = __half2float(__low2half(hh));
    float h1 = __half2float(__high2half(hh));
    lo = pack2h(f0 - h0, f1 - h1);
    hi = h;
}

// ---------------- tiny kernels ----------------
__global__ void zero_cnt_kernel() {
    g_cnt[blockIdx.x*blockDim.x + threadIdx.x] = 0;
}
__global__ void count_kernel(const int* __restrict__ n_id) {
    atomicAdd(&g_cnt[n_id[blockIdx.x*blockDim.x + threadIdx.x]], 1);
}

// deterministic compaction scan
__global__ void scan_kernel() {
    __shared__ int ps[256];
    const int t = threadIdx.x;
    const int base = t * 32;
    int loc = 0;
    #pragma unroll
    for (int i = 0; i < 32; i++) loc += (g_cnt[base + i] > 0);
    ps[t] = loc;
    __syncthreads();
    for (int d = 1; d < 256; d <<= 1) {
        int v = (t >= d) ? ps[t - d] : 0;
        __syncthreads();
        ps[t] += v;
        __syncthreads();
    }
    int pos = ps[t] - loc;
    for (int i = 0; i < 32; i++) {
        int r = base + i;
        if (g_cnt[r] > 0) { g_nz[pos] = r; g_rank[r] = pos; pos++; }
    }
    if (t == 255) {
        int nnz = ps[255];
        g_nnz = nnz;
        int npad = (nnz + 63) & ~63;
        g_npad = npad;
        g_nm = npad >> 6;
    }
    __syncthreads();
    int nnz = g_nnz;
    for (int j = nnz + t; j < NTOT; j += 256) g_nz[j] = 0;
}

// ---------------- transpose + fp16 pack (coalesced stores) ----------------
// SRC 0: x full original. SRC 2/3: g_Dk compact rows, zero-pad to npad.
template<int C, int SRC>
__global__ __launch_bounds__(256) void tsplit(const float* __restrict__ xext)
{
    const float* in;
    unsigned short* xo;
    if (SRC == 0)      { in = xext;    xo = g_xt; }
    else if (SRC == 2) { in = g_Dk[0]; xo = g_dt[0]; }
    else               { in = g_Dk[1]; xo = g_dt[1]; }

    const int t  = threadIdx.x;
    const int r0 = blockIdx.x * 64;
    int lim = NTOT;
    if (SRC != 0) {
        if (r0 >= g_npad) return;
        lim = g_nnz;
    }

    __shared__ float tile[64][C + 4];
    constexpr int F4 = C / 4;
    #pragma unroll
    for (int i = 0; i < 64*F4/256; i++) {
        int u = t + i*256;
        int row = u / F4, c4 = u % F4;
        if (SRC == 0 || r0 + row < lim) {
            float4 v = *(const float4*)&in[(size_t)(r0+row)*C + c4*4];
            tile[row][c4*4+0] = v.x; tile[row][c4*4+1] = v.y;
            tile[row][c4*4+2] = v.z; tile[row][c4*4+3] = v.w;
        } else {
            tile[row][c4*4+0] = 0.f; tile[row][c4*4+1] = 0.f;
            tile[row][c4*4+2] = 0.f; tile[row][c4*4+3] = 0.f;
        }
    }
    __syncthreads();
    const int wid = t >> 5, lane = t & 31;
    const int r = 2*lane;
    for (int c = wid; c < C; c += 8) {
        *(unsigned*)&xo[(size_t)c*NTOT + r0 + r] = pack2h(tile[r][c], tile[r+1][c]);
    }
}

// ---- fused: A_c[j] = x[nz[j]] - tau*sum(P); act (compact fp16) = cnt*A ----
__global__ __launch_bounds__(256) void combine_tsplit(const float* __restrict__ x,
                                                      const float* __restrict__ taup)
{
    const int t  = threadIdx.x;
    const int r0 = blockIdx.x * 64;
    if (r0 >= g_npad) return;
    const int nnz = g_nnz;
    const float tv = taup[0];

    __shared__ float tile[64][DD + 4];
    #pragma unroll
    for (int i = 0; i < 8; i++) {
        int u = t + i*256;
        int row = u >> 5, c4 = u & 31;
        int j = r0 + row;
        if (j < nnz) {
            int orow = g_nz[j];
            float cn = (float)g_cnt[orow];
            size_t oc = (size_t)j*DD + c4*4;
            float4 xv = *(const float4*)&x[(size_t)orow*DD + c4*4];
            float4 ps = make_float4(0.f, 0.f, 0.f, 0.f);
            #pragma unroll
            for (int s = 0; s < SL; s++) {
                float4 p = *(const float4*)&g_P[s][oc];
                ps.x += p.x; ps.y += p.y; ps.z += p.z; ps.w += p.w;
            }
            float4 a;
            a.x = xv.x - tv*ps.x; a.y = xv.y - tv*ps.y;
            a.z = xv.z - tv*ps.z; a.w = xv.w - tv*ps.w;
            *(float4*)&g_A[oc] = a;
            tile[row][c4*4+0] = cn*a.x; tile[row][c4*4+1] = cn*a.y;
            tile[row][c4*4+2] = cn*a.z; tile[row][c4*4+3] = cn*a.w;
        } else {
            tile[row][c4*4+0] = 0.f; tile[row][c4*4+1] = 0.f;
            tile[row][c4*4+2] = 0.f; tile[row][c4*4+3] = 0.f;
        }
    }
    __syncthreads();
    const int wid = t >> 5, lane = t & 31;
    const int r = 2*lane;
    for (int c = wid; c < DD; c += 8) {
        *(unsigned*)&g_act[(size_t)c*NTOT + r0 + r] = pack2h(tile[r][c], tile[r+1][c]);
    }
}

// ---------------- HMMA GEMM: fp16 2-limb Mat x single-fp16 X ----------------
// MODE 0: Mat=L rows nz, X=xt (full K)      -> g_P[s]
// MODE 1: Mat=K[y] rows+cols nz (gather+split, ALSO writes g_kc), X=act -> g_PB[y][s]
// MODE 2: A = g_kc (cp.async), X=dt         -> g_PE[y][s]
template<int NB, int MODE>
__global__ __launch_bounds__(256, 2) void gemm_hmma(const float* __restrict__ Mb)
{
    extern __shared__ char smem[];
    __shared__ int s_nzr[64];
    constexpr int NF  = NB / 32;
    constexpr int XSZ = NB * 128;          // single-limb X stage bytes
    constexpr int XU  = NB / 32;
    constexpr int STG = 16384 + XSZ;       // A(hi+lo) + X per stage

    const int t = threadIdx.x, lane = t & 31, w = t >> 5;
    const int wm = w & 1, wn = w >> 1;
    const int NM   = g_nm;
    const int NPAD = g_npad;
    const int NT   = (MODE == 0) ? NM : 2*NM;
    const int NC   = (MODE == 0) ? 128 : NM;
    const unsigned su = smem_u32(smem);

    for (int q = blockIdx.x; q < NT*SL; q += gridDim.x) {
        const int tile = q % NT;
        const int s    = q / NT;
        const int m    = (MODE == 0) ? tile : (tile % NM);
        const int y    = (MODE == 0) ? 0    : (tile / NM);
        const int c0   = (s * NC) / SL;
        const int c1   = ((s + 1) * NC) / SL;

        const float* Mat = (MODE == 0) ? Mb : Mb + (size_t)y * NTOT * NTOT;
        const unsigned short* X;
        if (MODE == 0)      X = g_xt;
        else if (MODE == 1) X = g_act;
        else                X = g_dt[y];

        __syncthreads();   // smem stage + s_nzr reuse across items
        if (MODE != 2) {
            if (t < 64) s_nzr[t] = g_nz[m*64 + t];
            __syncthreads();
        }

        float acc[2][NF][4];
        #pragma unroll
        for (int mf = 0; mf < 2; mf++)
            #pragma unroll
            for (int nf = 0; nf < NF; nf++)
                #pragma unroll
                for (int j = 0; j < 4; j++) acc[mf][nf][j] = 0.f;

        float mv[16];

        auto LDG_MV = [&](int c) {
            if (MODE == 2) return;
            const int k0 = c * 64;
            #pragma unroll
            for (int i = 0; i < 4; i++) {
                int u = t + (i << 8);
                int row = u >> 4, qd = u & 15;
                size_t rbase = (size_t)s_nzr[row] * NTOT;
                if (MODE == 0) {
                    *(float4*)&mv[i*4] = *(const float4*)&Mat[rbase + k0 + (qd << 2)];
                } else {
                    #pragma unroll
                    for (int j = 0; j < 4; j++)
                        mv[i*4+j] = Mat[rbase + g_nz[k0 + qd*4 + j]];
                }
            }
        };
        auto FILL = [&](int c, int st) {
            const int k0 = c * 64;
            if (MODE == 2) {
                const unsigned aHb = su + st*STG;
                #pragma unroll
                for (int i = 0; i < 2; i++) {
                    int u = t + (i << 8);
                    int row = u >> 3, j8 = u & 7;
                    unsigned off = SWZ((unsigned)(row*128 + j8*16));
                    size_t o = (size_t)(m*64 + row)*NPAD + k0 + j8*8;
                    CP16(aHb + off,        (const void*)&g_kc_hi[y][o]);
                    CP16(aHb + 8192 + off, (const void*)&g_kc_lo[y][o]);
                }
            } else {
                char* aH = smem + st*STG;
                char* aL = aH + 8192;
                #pragma unroll
                for (int i = 0; i < 4; i++) {
                    int u = t + (i << 8);
                    int row = u >> 4, qd = u & 15;
                    unsigned h0, l0, h1, l1;
                    split2h(mv[i*4+0], mv[i*4+1], h0, l0);
                    split2h(mv[i*4+2], mv[i*4+3], h1, l1);
                    unsigned off = SWZ((unsigned)(row*128 + qd*8));
                    *(uint2*)(aH + off) = make_uint2(h0, h1);
                    *(uint2*)(aL + off) = make_uint2(l0, l1);
                    if (MODE == 1) {
                        size_t ko = (size_t)(m*64 + row)*NPAD + k0 + qd*4;
                        *(uint2*)&g_kc_hi[y][ko] = make_uint2(h0, h1);
                        *(uint2*)&g_kc_lo[y][ko] = make_uint2(l0, l1);
                    }
                }
            }
            const unsigned xb = su + st*STG + 16384;
            #pragma unroll
            for (int i = 0; i < XU; i++) {
                int u = t + (i << 8);
                unsigned off = SWZ((unsigned)((u >> 3)*128 + (u & 7)*16));
                size_t o = (size_t)(u >> 3)*NTOT + k0 + ((u & 7) << 3);
                CP16(xb + off, (const void*)&X[o]);
            }
            CP_COMMIT();
        };

        LDG_MV(c0);
        FILL(c0, 0);
        if (c0 + 1 < c1) LDG_MV(c0 + 1);
        CP_WAIT0();
        __syncthreads();

        int st = 0;
        for (int c = c0; c < c1; c++) {
            const unsigned aHb = su + st*STG;
            const unsigned aLb = aHb + 8192;
            const unsigned xb  = aHb + 16384;

            auto KSTEP = [&](int kk) {
                const int kc2 = kk * 32;
                unsigned ah[2][4], al[2][4];
                #pragma unroll
                for (int mf = 0; mf < 2; mf++) {
                    int row = wm*32 + mf*16 + (lane & 15);
                    int kb  = kc2 + ((lane >> 4) << 4);
                    unsigned off = SWZ((unsigned)(row*128 + kb));
                    LDSM4(ah[mf][0], ah[mf][1], ah[mf][2], ah[mf][3], aHb + off);
                    LDSM4(al[mf][0], al[mf][1], al[mf][2], al[mf][3], aLb + off);
                }
                unsigned bx[NF][2];
                #pragma unroll
                for (int g = 0; g < NF/2; g++) {
                    int n  = wn*(NB/4) + g*16 + ((lane >> 4) << 3) + (lane & 7);
                    int kb = kc2 + (((lane >> 3) & 1) << 4);
                    unsigned off = SWZ((unsigned)(n*128 + kb));
                    LDSM4(bx[2*g][0], bx[2*g][1], bx[2*g+1][0], bx[2*g+1][1], xb + off);
                }
                #pragma unroll
                for (int nf = 0; nf < NF; nf++)
                    #pragma unroll
                    for (int mf = 0; mf < 2; mf++) MMA16816(acc[mf][nf], ah[mf], bx[nf]);
                #pragma unroll
                for (int nf = 0; nf < NF; nf++)
                    #pragma unroll
                    for (int mf = 0; mf < 2; mf++) MMA16816(acc[mf][nf], al[mf], bx[nf]);
            };

            KSTEP(0);
            KSTEP(1);
            if (c + 1 < c1) {
                FILL(c + 1, st ^ 1);
                if (c + 2 < c1) LDG_MV(c + 2);
            }
            KSTEP(2);
            KSTEP(3);
            if (c + 1 < c1) {
                CP_WAIT0();
                __syncthreads();
            }
            st ^= 1;
        }

        // epilogue: write this slice's partial (compact rows)
        const int gid = lane >> 2, tig = lane & 3;
        float* O;
        int stride;
        if (MODE == 0)      { O = g_P[s];     stride = DD; }
        else if (MODE == 1) { O = g_PB[y][s]; stride = DD; }
        else                { O = g_PE[y][s]; stride = EMBD; }
        #pragma unroll
        for (int mf = 0; mf < 2; mf++) {
            int r = m*64 + wm*32 + mf*16 + gid;
            #pragma unroll
            for (int nf = 0; nf < NF; nf++) {
                int cc = wn*(NB/4) + nf*8 + 2*tig;
                *(float2*)&O[(size_t)r*stride + cc]     = make_float2(acc[mf][nf][0], acc[mf][nf][1]);
                *(float2*)&O[(size_t)(r+8)*stride + cc] = make_float2(acc[mf][nf][2], acc[mf][nf][3]);
            }
        }
    }
}

// ---------------- small fused projections (compact rows) ----------------
__global__ __launch_bounds__(256) void zd_kernel(const float* __restrict__ W)
{
    const int t  = threadIdx.x;
    const int r0 = blockIdx.x * 32;
    if (r0 >= g_npad) return;

    __shared__ float As [32][128];
    __shared__ float B0s[32][128];
    __shared__ float B1s[32][128];

    const int e  = t & 63;
    const int ry = t >> 6;

    #pragma unroll
    for (int i = 0; i < 4; i++) {
        int f = t + i*256;
        int row = f >> 5, c4 = f & 31;
        size_t o = (size_t)(r0+row)*DD + 4*c4;
        *(float4*)&As[row][4*c4] = *(const float4*)&g_A[o];
        float4 b0 = make_float4(0,0,0,0), b1 = make_float4(0,0,0,0);
        #pragma unroll
        for (int s = 0; s < SL; s++) {
            float4 p0 = *(const float4*)&g_PB[0][s][o];
            float4 p1 = *(const float4*)&g_PB[1][s][o];
            b0.x += p0.x; b0.y += p0.y; b0.z += p0.z; b0.w += p0.w;
            b1.x += p1.x; b1.y += p1.y; b1.z += p1.z; b1.w += p1.w;
        }
        *(float4*)&B0s[row][4*c4] = b0;
        *(float4*)&B1s[row][4*c4] = b1;
    }
    __syncthreads();

    float accZ[8], accD0[8], accD1[8];
    #pragma unroll
    for (int s = 0; s < 8; s++) { accZ[s] = 0.f; accD0[s] = 0.f; accD1[s] = 0.f; }

    for (int f = 0; f < 128; f++) {
        float wz0 = W[( 0  + f)*64 + e];
        float wz1 = W[(128 + f)*64 + e];
        float wz2 = W[(256 + f)*64 + e];
        float w00 = W[(384 + f)*64 + e];
        float w01 = W[(512 + f)*64 + e];
        float w10 = W[(640 + f)*64 + e];
        float w11 = W[(768 + f)*64 + e];
        #pragma unroll
        for (int s = 0; s < 8; s++) {
            int r = ry + 4*s;
            float a  = As [r][f];
            float b0 = B0s[r][f];
            float b1 = B1s[r][f];
            accZ [s] += a*wz0 + b0*wz1 + b1*wz2;
            accD0[s] += b0*w00 + b1*w01;
            accD1[s] += b0*w10 + b1*w11;
        }
    }
    #pragma unroll
    for (int s = 0; s < 8; s++) {
        int j = r0 + ry + 4*s;
        float cn = (float)g_cnt[g_nz[j]];
        g_Z    [(size_t)j*EMBD + e] = accZ[s];
        g_Dk[0][(size_t)j*EMBD + e] = cn * accD0[s];
        g_Dk[1][(size_t)j*EMBD + e] = cn * accD1[s];
    }
}

__global__ void final_kernel(const int* __restrict__ n_id,
                             const float* __restrict__ b,
                             float* __restrict__ out)
{
    int idx = blockIdx.x*blockDim.x + threadIdx.x;
    int j = idx >> 6, e = idx & 63;
    int cr = g_rank[n_id[j]];
    size_t zr = (size_t)cr*EMBD + e;
    float ev = 0.f;
    #pragma unroll
    for (int s = 0; s < SL; s++) ev += g_PE[0][s][zr] + g_PE[1][s][zr];
    out[idx] = tanhf(g_Z[zr] + ev + b[e]);
}

// ---------------- launch ----------------
extern "C" void kernel_launch(void* const* d_in, const int* in_sizes, int n_in,
                              void* d_out, int out_size)
{
    const float* x    = (const float*)d_in[0];
    const float* K    = (const float*)d_in[1];
    const float* L    = (const float*)d_in[2];
    const float* tau  = (const float*)d_in[3];
    const float* W    = (const float*)d_in[4];
    const float* b    = (const float*)d_in[5];
    const int*   n_id = (const int*)  d_in[6];
    float* out = (float*)d_out;

    const int SM128 = 2*(16384 + 128*128);   // 65536
    const int SM64  = 2*(16384 + 64*128);    // 49152
    cudaFuncSetAttribute(gemm_hmma<128,0>, cudaFuncAttributeMaxDynamicSharedMemorySize, SM128);
    cudaFuncSetAttribute(gemm_hmma<128,1>, cudaFuncAttributeMaxDynamicSharedMemorySize, SM128);
    cudaFuncSetAttribute(gemm_hmma<64,2>,  cudaFuncAttributeMaxDynamicSharedMemorySize, SM64);

    const int GRID = 304;   // 2 CTAs/SM x 152 SMs

    zero_cnt_kernel<<<NTOT/256, 256>>>();
    count_kernel   <<<NTOT/256, 256>>>(n_id);
    scan_kernel    <<<1, 256>>>();

    // x^T fp16 (full); L@x partials on nz rows (7 K-slices); fused combine
    tsplit<128,0><<<NTOT/64, 256>>>(x);
    gemm_hmma<128,0><<<GRID, 256, SM128>>>(L);
    combine_tsplit<<<NTOT/64, 256>>>(x, tau);

    // B_k = K[k] @ Ac (rows+cols compact; gathers K once, streams fp16 K out)
    gemm_hmma<128,1><<<GRID, 256, SM128>>>(K);

    // Z and D_k (sums B partials inline)
    zd_kernel<<<NTOT/32, 256>>>(W);

    // Dk^T fp16 (compact, zero-padded); E_k = K[k] @ D_k (A via cp.async)
    tsplit<64,2><<<NTOT/64, 256>>>(nullptr);
    tsplit<64,3><<<NTOT/64, 256>>>(nullptr);
    gemm_hmma<64,2><<<GRID, 256, SM64>>>(K);

    final_kernel<<<(NTOT*EMBD)/256, 256>>>(n_id, b, out);
}

// round 16
// speedup vs baseline: 1.5673x; 1.1593x over previous
#include <cuda_runtime.h>
#include <cuda_fp16.h>
#include <math.h>

#define NTOT 8192
#define DD   128
#define EMBD 64
#define SL   7

// ---------------- scratch (device globals; no allocations) ----------------
__device__ float g_A [NTOT*DD];           // compact rows
__device__ float g_P [SL][NTOT*DD];       // L-pass K-slice partials
__device__ float g_PB[2][SL][NTOT*DD];    // B-pass partials
__device__ float g_PE[2][SL][NTOT*EMBD];  // E-pass partials
__device__ float g_Dk[2][NTOT*EMBD];      // compact rows
__device__ float g_Z [NTOT*EMBD];         // compact rows
__device__ int   g_cnt[NTOT];
__device__ int   g_nz[NTOT];              // nz row list (padded with 0)
__device__ int   g_rank[NTOT];            // original row -> compact index
__device__ int   g_nnz, g_npad, g_nm;

// transposed fp16 X operands ([C][NTOT]; xt original idx, act/dt compact)
__device__ unsigned short g_xt [DD*NTOT];
__device__ unsigned short g_act[DD*NTOT];
__device__ unsigned short g_dt [2][EMBD*NTOT];

// compacted fp16 K (rows+cols nz, row stride = npad), written by B-pass
__device__ unsigned short g_kc[2][(size_t)NTOT*NTOT];

// ---------------- helpers ----------------
__device__ __forceinline__ unsigned smem_u32(const void* p) {
    unsigned a;
    asm("{ .reg .u64 t; cvta.to.shared.u64 t, %1; cvt.u32.u64 %0, t; }" : "=r"(a) : "l"(p));
    return a;
}
#define SWZ(o) ((o) ^ (((o) >> 3) & 0x70))

#define LDSM4(d0,d1,d2,d3,addr) \
    asm volatile("ldmatrix.sync.aligned.m8n8.x4.shared.b16 {%0,%1,%2,%3}, [%4];" \
        : "=r"(d0), "=r"(d1), "=r"(d2), "=r"(d3) : "r"(addr))

#define MMA16816(c, a, b) \
    asm volatile("mma.sync.aligned.m16n8k16.row.col.f32.f16.f16.f32 " \
        "{%0,%1,%2,%3},{%4,%5,%6,%7},{%8,%9},{%0,%1,%2,%3};" \
        : "+f"((c)[0]), "+f"((c)[1]), "+f"((c)[2]), "+f"((c)[3]) \
        : "r"((a)[0]), "r"((a)[1]), "r"((a)[2]), "r"((a)[3]), \
          "r"((b)[0]), "r"((b)[1]))

#define CP16(dst, src) \
    asm volatile("cp.async.cg.shared.global [%0], [%1], 16;" :: "r"(dst), "l"(src))
#define CP_COMMIT() asm volatile("cp.async.commit_group;" ::: "memory")
#define CP_WAIT0()  asm volatile("cp.async.wait_group 0;" ::: "memory")

// pack float pair to f16x2 (rn)
__device__ __forceinline__ unsigned pack2h(float f0, float f1) {
    unsigned r;
    asm("cvt.rn.f16x2.f32 %0, %1, %2;" : "=r"(r) : "f"(f1), "f"(f0));
    return r;
}

// ---------------- tiny kernels ----------------
__global__ void zero_cnt_kernel() {
    g_cnt[blockIdx.x*blockDim.x + threadIdx.x] = 0;
}
__global__ void count_kernel(const int* __restrict__ n_id) {
    atomicAdd(&g_cnt[n_id[blockIdx.x*blockDim.x + threadIdx.x]], 1);
}

// deterministic compaction scan
__global__ void scan_kernel() {
    __shared__ int ps[256];
    const int t = threadIdx.x;
    const int base = t * 32;
    int loc = 0;
    #pragma unroll
    for (int i = 0; i < 32; i++) loc += (g_cnt[base + i] > 0);
    ps[t] = loc;
    __syncthreads();
    for (int d = 1; d < 256; d <<= 1) {
        int v = (t >= d) ? ps[t - d] : 0;
        __syncthreads();
        ps[t] += v;
        __syncthreads();
    }
    int pos = ps[t] - loc;
    for (int i = 0; i < 32; i++) {
        int r = base + i;
        if (g_cnt[r] > 0) { g_nz[pos] = r; g_rank[r] = pos; pos++; }
    }
    if (t == 255) {
        int nnz = ps[255];
        g_nnz = nnz;
        int npad = (nnz + 63) & ~63;
        g_npad = npad;
        g_nm = npad >> 6;
    }
    __syncthreads();
    int nnz = g_nnz;
    for (int j = nnz + t; j < NTOT; j += 256) g_nz[j] = 0;
}

// ---------------- transpose + fp16 pack (coalesced stores) ----------------
// SRC 0: x full original. SRC 2/3: g_Dk compact rows, zero-pad to npad.
template<int C, int SRC>
__global__ __launch_bounds__(256) void tsplit(const float* __restrict__ xext)
{
    const float* in;
    unsigned short* xo;
    if (SRC == 0)      { in = xext;    xo = g_xt; }
    else if (SRC == 2) { in = g_Dk[0]; xo = g_dt[0]; }
    else               { in = g_Dk[1]; xo = g_dt[1]; }

    const int t  = threadIdx.x;
    const int r0 = blockIdx.x * 64;
    int lim = NTOT;
    if (SRC != 0) {
        if (r0 >= g_npad) return;
        lim = g_nnz;
    }

    __shared__ float tile[64][C + 4];
    constexpr int F4 = C / 4;
    #pragma unroll
    for (int i = 0; i < 64*F4/256; i++) {
        int u = t + i*256;
        int row = u / F4, c4 = u % F4;
        if (SRC == 0 || r0 + row < lim) {
            float4 v = *(const float4*)&in[(size_t)(r0+row)*C + c4*4];
            tile[row][c4*4+0] = v.x; tile[row][c4*4+1] = v.y;
            tile[row][c4*4+2] = v.z; tile[row][c4*4+3] = v.w;
        } else {
            tile[row][c4*4+0] = 0.f; tile[row][c4*4+1] = 0.f;
            tile[row][c4*4+2] = 0.f; tile[row][c4*4+3] = 0.f;
        }
    }
    __syncthreads();
    const int wid = t >> 5, lane = t & 31;
    const int r = 2*lane;
    for (int c = wid; c < C; c += 8) {
        *(unsigned*)&xo[(size_t)c*NTOT + r0 + r] = pack2h(tile[r][c], tile[r+1][c]);
    }
}

// ---- fused: A_c[j] = x[nz[j]] - tau*sum(P); act (compact fp16) = cnt*A ----
__global__ __launch_bounds__(256) void combine_tsplit(const float* __restrict__ x,
                                                      const float* __restrict__ taup)
{
    const int t  = threadIdx.x;
    const int r0 = blockIdx.x * 64;
    if (r0 >= g_npad) return;
    const int nnz = g_nnz;
    const float tv = taup[0];

    __shared__ float tile[64][DD + 4];
    #pragma unroll
    for (int i = 0; i < 8; i++) {
        int u = t + i*256;
        int row = u >> 5, c4 = u & 31;
        int j = r0 + row;
        if (j < nnz) {
            int orow = g_nz[j];
            float cn = (float)g_cnt[orow];
            size_t oc = (size_t)j*DD + c4*4;
            float4 xv = *(const float4*)&x[(size_t)orow*DD + c4*4];
            float4 ps = make_float4(0.f, 0.f, 0.f, 0.f);
            #pragma unroll
            for (int s = 0; s < SL; s++) {
                float4 p = *(const float4*)&g_P[s][oc];
                ps.x += p.x; ps.y += p.y; ps.z += p.z; ps.w += p.w;
            }
            float4 a;
            a.x = xv.x - tv*ps.x; a.y = xv.y - tv*ps.y;
            a.z = xv.z - tv*ps.z; a.w = xv.w - tv*ps.w;
            *(float4*)&g_A[oc] = a;
            tile[row][c4*4+0] = cn*a.x; tile[row][c4*4+1] = cn*a.y;
            tile[row][c4*4+2] = cn*a.z; tile[row][c4*4+3] = cn*a.w;
        } else {
            tile[row][c4*4+0] = 0.f; tile[row][c4*4+1] = 0.f;
            tile[row][c4*4+2] = 0.f; tile[row][c4*4+3] = 0.f;
        }
    }
    __syncthreads();
    const int wid = t >> 5, lane = t & 31;
    const int r = 2*lane;
    for (int c = wid; c < DD; c += 8) {
        *(unsigned*)&g_act[(size_t)c*NTOT + r0 + r] = pack2h(tile[r][c], tile[r+1][c]);
    }
}

// ---------------- HMMA GEMM: single fp16 limb Mat x single fp16 X -----------
// MODE 0: Mat=L rows nz, X=xt (full K)      -> g_P[s]
// MODE 1: Mat=K[y] rows+cols nz (gather+pack, ALSO writes g_kc), X=act -> g_PB[y][s]
// MODE 2: A = g_kc (cp.async), X=dt         -> g_PE[y][s]
template<int NB, int MODE>
__global__ __launch_bounds__(256, 2) void gemm_hmma(const float* __restrict__ Mb)
{
    extern __shared__ char smem[];
    __shared__ int s_nzr[64];
    constexpr int NF  = NB / 32;
    constexpr int XSZ = NB * 128;          // X stage bytes
    constexpr int XU  = NB / 32;
    constexpr int STG = 8192 + XSZ;        // A(hi) + X per stage

    const int t = threadIdx.x, lane = t & 31, w = t >> 5;
    const int wm = w & 1, wn = w >> 1;
    const int NM   = g_nm;
    const int NPAD = g_npad;
    const int NT   = (MODE == 0) ? NM : 2*NM;
    const int NC   = (MODE == 0) ? 128 : NM;
    const unsigned su = smem_u32(smem);

    for (int q = blockIdx.x; q < NT*SL; q += gridDim.x) {
        const int tile = q % NT;
        const int s    = q / NT;
        const int m    = (MODE == 0) ? tile : (tile % NM);
        const int y    = (MODE == 0) ? 0    : (tile / NM);
        const int c0   = (s * NC) / SL;
        const int c1   = ((s + 1) * NC) / SL;

        const float* Mat = (MODE == 0) ? Mb : Mb + (size_t)y * NTOT * NTOT;
        const unsigned short* X;
        if (MODE == 0)      X = g_xt;
        else if (MODE == 1) X = g_act;
        else                X = g_dt[y];

        __syncthreads();   // smem stage + s_nzr reuse across items
        if (MODE != 2) {
            if (t < 64) s_nzr[t] = g_nz[m*64 + t];
            __syncthreads();
        }

        float acc[2][NF][4];
        #pragma unroll
        for (int mf = 0; mf < 2; mf++)
            #pragma unroll
            for (int nf = 0; nf < NF; nf++)
                #pragma unroll
                for (int j = 0; j < 4; j++) acc[mf][nf][j] = 0.f;

        float mv[16];

        auto LDG_MV = [&](int c) {
            if (MODE == 2) return;
            const int k0 = c * 64;
            #pragma unroll
            for (int i = 0; i < 4; i++) {
                int u = t + (i << 8);
                int row = u >> 4, qd = u & 15;
                size_t rbase = (size_t)s_nzr[row] * NTOT;
                if (MODE == 0) {
                    *(float4*)&mv[i*4] = *(const float4*)&Mat[rbase + k0 + (qd << 2)];
                } else {
                    #pragma unroll
                    for (int j = 0; j < 4; j++)
                        mv[i*4+j] = Mat[rbase + g_nz[k0 + qd*4 + j]];
                }
            }
        };
        auto FILL = [&](int c, int st) {
            const int k0 = c * 64;
            if (MODE == 2) {
                const unsigned ab = su + st*STG;
                #pragma unroll
                for (int i = 0; i < 2; i++) {
                    int u = t + (i << 8);
                    int row = u >> 3, j8 = u & 7;
                    unsigned off = SWZ((unsigned)(row*128 + j8*16));
                    size_t o = (size_t)(m*64 + row)*NPAD + k0 + j8*8;
                    CP16(ab + off, (const void*)&g_kc[y][o]);
                }
            } else {
                char* aB = smem + st*STG;
                #pragma unroll
                for (int i = 0; i < 4; i++) {
                    int u = t + (i << 8);
                    int row = u >> 4, qd = u & 15;
                    unsigned h0 = pack2h(mv[i*4+0], mv[i*4+1]);
                    unsigned h1 = pack2h(mv[i*4+2], mv[i*4+3]);
                    unsigned off = SWZ((unsigned)(row*128 + qd*8));
                    *(uint2*)(aB + off) = make_uint2(h0, h1);
                    if (MODE == 1) {
                        size_t ko = (size_t)(m*64 + row)*NPAD + k0 + qd*4;
                        *(uint2*)&g_kc[y][ko] = make_uint2(h0, h1);
                    }
                }
            }
            const unsigned xb = su + st*STG + 8192;
            #pragma unroll
            for (int i = 0; i < XU; i++) {
                int u = t + (i << 8);
                unsigned off = SWZ((unsigned)((u >> 3)*128 + (u & 7)*16));
                size_t o = (size_t)(u >> 3)*NTOT + k0 + ((u & 7) << 3);
                CP16(xb + off, (const void*)&X[o]);
            }
            CP_COMMIT();
        };

        LDG_MV(c0);
        FILL(c0, 0);
        if (c0 + 1 < c1) LDG_MV(c0 + 1);
        CP_WAIT0();
        __syncthreads();

        int st = 0;
        for (int c = c0; c < c1; c++) {
            const unsigned ab = su + st*STG;
            const unsigned xb = ab + 8192;

            auto KSTEP = [&](int kk) {
                const int kc2 = kk * 32;
                unsigned ah[2][4];
                #pragma unroll
                for (int mf = 0; mf < 2; mf++) {
                    int row = wm*32 + mf*16 + (lane & 15);
                    int kb  = kc2 + ((lane >> 4) << 4);
                    unsigned off = SWZ((unsigned)(row*128 + kb));
                    LDSM4(ah[mf][0], ah[mf][1], ah[mf][2], ah[mf][3], ab + off);
                }
                unsigned bx[NF][2];
                #pragma unroll
                for (int g = 0; g < NF/2; g++) {
                    int n  = wn*(NB/4) + g*16 + ((lane >> 4) << 3) + (lane & 7);
                    int kb = kc2 + (((lane >> 3) & 1) << 4);
                    unsigned off = SWZ((unsigned)(n*128 + kb));
                    LDSM4(bx[2*g][0], bx[2*g][1], bx[2*g+1][0], bx[2*g+1][1], xb + off);
                }
                #pragma unroll
                for (int nf = 0; nf < NF; nf++)
                    #pragma unroll
                    for (int mf = 0; mf < 2; mf++) MMA16816(acc[mf][nf], ah[mf], bx[nf]);
            };

            KSTEP(0);
            KSTEP(1);
            if (c + 1 < c1) {
                FILL(c + 1, st ^ 1);
                if (c + 2 < c1) LDG_MV(c + 2);
            }
            KSTEP(2);
            KSTEP(3);
            if (c + 1 < c1) {
                CP_WAIT0();
                __syncthreads();
            }
            st ^= 1;
        }

        // epilogue: write this slice's partial (compact rows)
        const int gid = lane >> 2, tig = lane & 3;
        float* O;
        int stride;
        if (MODE == 0)      { O = g_P[s];     stride = DD; }
        else if (MODE == 1) { O = g_PB[y][s]; stride = DD; }
        else                { O = g_PE[y][s]; stride = EMBD; }
        #pragma unroll
        for (int mf = 0; mf < 2; mf++) {
            int r = m*64 + wm*32 + mf*16 + gid;
            #pragma unroll
            for (int nf = 0; nf < NF; nf++) {
                int cc = wn*(NB/4) + nf*8 + 2*tig;
                *(float2*)&O[(size_t)r*stride + cc]     = make_float2(acc[mf][nf][0], acc[mf][nf][1]);
                *(float2*)&O[(size_t)(r+8)*stride + cc] = make_float2(acc[mf][nf][2], acc[mf][nf][3]);
            }
        }
    }
}

// ---------------- small fused projections (compact rows) ----------------
__global__ __launch_bounds__(256) void zd_kernel(const float* __restrict__ W)
{
    const int t  = threadIdx.x;
    const int r0 = blockIdx.x * 32;
    if (r0 >= g_npad) return;

    __shared__ float As [32][128];
    __shared__ float B0s[32][128];
    __shared__ float B1s[32][128];

    const int e  = t & 63;
    const int ry = t >> 6;

    #pragma unroll
    for (int i = 0; i < 4; i++) {
        int f = t + i*256;
        int row = f >> 5, c4 = f & 31;
        size_t o = (size_t)(r0+row)*DD + 4*c4;
        *(float4*)&As[row][4*c4] = *(const float4*)&g_A[o];
        float4 b0 = make_float4(0,0,0,0), b1 = make_float4(0,0,0,0);
        #pragma unroll
        for (int s = 0; s < SL; s++) {
            float4 p0 = *(const float4*)&g_PB[0][s][o];
            float4 p1 = *(const float4*)&g_PB[1][s][o];
            b0.x += p0.x; b0.y += p0.y; b0.z += p0.z; b0.w += p0.w;
            b1.x += p1.x; b1.y += p1.y; b1.z += p1.z; b1.w += p1.w;
        }
        *(float4*)&B0s[row][4*c4] = b0;
        *(float4*)&B1s[row][4*c4] = b1;
    }
    __syncthreads();

    float accZ[8], accD0[8], accD1[8];
    #pragma unroll
    for (int s = 0; s < 8; s++) { accZ[s] = 0.f; accD0[s] = 0.f; accD1[s] = 0.f; }

    for (int f = 0; f < 128; f++) {
        float wz0 = W[( 0  + f)*64 + e];
        float wz1 = W[(128 + f)*64 + e];
        float wz2 = W[(256 + f)*64 + e];
        float w00 = W[(384 + f)*64 + e];
        float w01 = W[(512 + f)*64 + e];
        float w10 = W[(640 + f)*64 + e];
        float w11 = W[(768 + f)*64 + e];
        #pragma unroll
        for (int s = 0; s < 8; s++) {
            int r = ry + 4*s;
            float a  = As [r][f];
            float b0 = B0s[r][f];
            float b1 = B1s[r][f];
            accZ [s] += a*wz0 + b0*wz1 + b1*wz2;
            accD0[s] += b0*w00 + b1*w01;
            accD1[s] += b0*w10 + b1*w11;
        }
    }
    #pragma unroll
    for (int s = 0; s < 8; s++) {
        int j = r0 + ry + 4*s;
        float cn = (float)g_cnt[g_nz[j]];
        g_Z    [(size_t)j*EMBD + e] = accZ[s];
        g_Dk[0][(size_t)j*EMBD + e] = cn * accD0[s];
        g_Dk[1][(size_t)j*EMBD + e] = cn * accD1[s];
    }
}

__global__ void final_kernel(const int* __restrict__ n_id,
                             const float* __restrict__ b,
                             float* __restrict__ out)
{
    int idx = blockIdx.x*blockDim.x + threadIdx.x;
    int j = idx >> 6, e = idx & 63;
    int cr = g_rank[n_id[j]];
    size_t zr = (size_t)cr*EMBD + e;
    float ev = 0.f;
    #pragma unroll
    for (int s = 0; s < SL; s++) ev += g_PE[0][s][zr] + g_PE[1][s][zr];
    out[idx] = tanhf(g_Z[zr] + ev + b[e]);
}

// ---------------- launch ----------------
extern "C" void kernel_launch(void* const* d_in, const int* in_sizes, int n_in,
                              void* d_out, int out_size)
{
    const float* x    = (const float*)d_in[0];
    const float* K    = (const float*)d_in[1];
    const float* L    = (const float*)d_in[2];
    const float* tau  = (const float*)d_in[3];
    const float* W    = (const float*)d_in[4];
    const float* b    = (const float*)d_in[5];
    const int*   n_id = (const int*)  d_in[6];
    float* out = (float*)d_out;

    const int SM128 = 2*(8192 + 128*128);   // 49152
    const int SM64  = 2*(8192 + 64*128);    // 32768
    cudaFuncSetAttribute(gemm_hmma<128,0>, cudaFuncAttributeMaxDynamicSharedMemorySize, SM128);
    cudaFuncSetAttribute(gemm_hmma<128,1>, cudaFuncAttributeMaxDynamicSharedMemorySize, SM128);
    cudaFuncSetAttribute(gemm_hmma<64,2>,  cudaFuncAttributeMaxDynamicSharedMemorySize, SM64);

    const int GRID = 304;   // 2 CTAs/SM x 152 SMs

    zero_cnt_kernel<<<NTOT/256, 256>>>();
    count_kernel   <<<NTOT/256, 256>>>(n_id);
    scan_kernel    <<<1, 256>>>();

    // x^T fp16 (full); L@x partials on nz rows (7 K-slices); fused combine
    tsplit<128,0><<<NTOT/64, 256>>>(x);
    gemm_hmma<128,0><<<GRID, 256, SM128>>>(L);
    combine_tsplit<<<NTOT/64, 256>>>(x, tau);

    // B_k = K[k] @ Ac (rows+cols compact; gathers K once, streams fp16 K out)
    gemm_hmma<128,1><<<GRID, 256, SM128>>>(K);

    // Z and D_k (sums B partials inline)
    zd_kernel<<<NTOT/32, 256>>>(W);

    // Dk^T fp16 (compact, zero-padded); E_k = K[k] @ D_k (A via cp.async)
    tsplit<64,2><<<NTOT/64, 256>>>(nullptr);
    tsplit<64,3><<<NTOT/64, 256>>>(nullptr);
    gemm_hmma<64,2><<<GRID, 256, SM64>>>(K);

    final_kernel<<<(NTOT*EMBD)/256, 256>>>(n_id, b, out);
}